// round 14
// baseline (speedup 1.0000x reference)
#include <cuda_runtime.h>
#include <math.h>
#include <stdint.h>

// ---------------- problem dims ----------------
#define Bq 4
#define Sq 1024
#define Eq 1024
#define Hh 16
#define Dd 64
#define FFq 4096
#define LN_EPS 1e-5f

// ---------------- scratch (device globals) ----------------
__device__ float g_V[Bq * Sq * Eq];
__device__ float g_K[Bq * Sq * Eq];
__device__ float g_Q[Bq * Sq * Eq];
__device__ float g_Vt[Bq * Sq * Eq];
__device__ float g_ctx[Bq * Sq * Eq];
__device__ float g_ao[Bq * Sq * Eq];
__device__ float g_x[Bq * Sq * Eq];
__device__ float g_h[(size_t)Bq * Sq * FFq];
__device__ float g_ff[Bq * Sq * Eq];
__device__ float g_Wvt[Eq * Eq];
__device__ float g_Wkt[Eq * Eq];
__device__ float g_Wqt[Eq * Eq];
__device__ float g_Wot[Eq * Eq];
__device__ float g_W1t[(size_t)Eq * FFq];
__device__ float g_W2t[(size_t)Eq * FFq];

// ---------------- PTX helpers ----------------
__device__ __forceinline__ uint32_t smem_u32(const void* p) {
    uint32_t a;
    asm("{ .reg .u64 t; cvta.to.shared.u64 t, %1; cvt.u32.u64 %0, t; }" : "=r"(a) : "l"(p));
    return a;
}
__device__ __forceinline__ void cp_async16(uint32_t dst, const void* src) {
    asm volatile("cp.async.ca.shared.global [%0], [%1], 16;" :: "r"(dst), "l"(src));
}
__device__ __forceinline__ void cp_commit() { asm volatile("cp.async.commit_group;"); }
template <int N>
__device__ __forceinline__ void cp_wait() { asm volatile("cp.async.wait_group %0;" :: "n"(N)); }

__device__ __forceinline__ float tf32r(float x) {
    uint32_t u;
    asm("cvt.rna.tf32.f32 %0, %1;" : "=r"(u) : "f"(x));
    return __uint_as_float(u);
}
__device__ __forceinline__ uint32_t tf32r_u(uint32_t x) {
    uint32_t u;
    asm("cvt.rna.tf32.f32 %0, %1;" : "=r"(u) : "f"(__uint_as_float(x)));
    return u;
}
__device__ __forceinline__ void ldsm_x4u(uint32_t* r, uint32_t addr) {
    asm volatile("ldmatrix.sync.aligned.m8n8.x4.shared.b16 {%0,%1,%2,%3}, [%4];"
        : "=r"(r[0]), "=r"(r[1]), "=r"(r[2]), "=r"(r[3]) : "r"(addr));
}
__device__ __forceinline__ void mma_tf32u(float* c, const uint32_t* a, uint32_t b0, uint32_t b1) {
    asm volatile(
        "mma.sync.aligned.m16n8k8.row.col.f32.tf32.tf32.f32 "
        "{%0,%1,%2,%3}, {%4,%5,%6,%7}, {%8,%9}, {%0,%1,%2,%3};"
        : "+f"(c[0]), "+f"(c[1]), "+f"(c[2]), "+f"(c[3])
        : "r"(a[0]), "r"(a[1]), "r"(a[2]), "r"(a[3]), "r"(b0), "r"(b1));
}

// ---------------- W[K,N] fp32 -> Wt[N,K] tf32-rounded ----------------
__global__ void __launch_bounds__(256)
transpose_tf32_kernel(const float* __restrict__ W, float* __restrict__ Wt, int K, int N)
{
    __shared__ float t[32][33];
    const int k0 = blockIdx.y * 32, n0 = blockIdx.x * 32;
    const int tx = threadIdx.x & 31, ty = threadIdx.x >> 5;
#pragma unroll
    for (int i = 0; i < 32; i += 8)
        t[ty + i][tx] = W[(size_t)(k0 + ty + i) * N + n0 + tx];
    __syncthreads();
#pragma unroll
    for (int i = 0; i < 32; i += 8)
        Wt[(size_t)(n0 + ty + i) * K + k0 + tx] = tf32r(t[tx][ty + i]);
}

// ---------------- per-batch transpose: Vt[(b*E+c)][k] = V[(b*S+k)][c] ----------------
__global__ void __launch_bounds__(256)
vtrans_kernel(const float* __restrict__ V, float* __restrict__ Vt)
{
    __shared__ float t[32][33];
    const int b = blockIdx.z;
    const int k0 = blockIdx.x * 32, c0 = blockIdx.y * 32;
    const int tx = threadIdx.x & 31, ty = threadIdx.x >> 5;
#pragma unroll
    for (int i = 0; i < 32; i += 8)
        t[ty + i][tx] = V[(size_t)(b * Sq + k0 + ty + i) * Eq + c0 + tx];
    __syncthreads();
#pragma unroll
    for (int i = 0; i < 32; i += 8)
        Vt[(size_t)(b * Eq + c0 + ty + i) * Sq + k0 + tx] = t[tx][ty + i];
}

// ---------------- tf32 MMA GEMM (R11 config + A-fragment rounding) ----------------
// CTA 128x128, kt=32, 2-stage, 8 warps 4Mx2N, ldmatrix feed, one barrier/k-tile.
// A fragments tf32-rounded in-register (rna; idempotent) -> no pre-round pass needed.
#define KT 32
#define PAD 36
#define GSMEM (2 * 2 * 128 * PAD * 4)   // 73728 B -> 2 CTAs/SM

__global__ void __launch_bounds__(256)
gemm_tf32(const float* __restrict__ A, const float* __restrict__ Bt,
          const float* __restrict__ bias, float* __restrict__ C,
          int M, int K, int N, int relu, int round_out)
{
    extern __shared__ float sm[];
    const int tid = threadIdx.x;
    const int wid = tid >> 5, lane = tid & 31;
    const int wm = wid & 3, wn = wid >> 2;
    const int row0 = blockIdx.y * 128;
    const int col0 = blockIdx.x * 128;

    const uint32_t sbase = smem_u32(sm);
    const uint32_t MATB = 128 * PAD * 4;

    float acc[2][8][4];
#pragma unroll
    for (int i = 0; i < 2; i++)
#pragma unroll
        for (int j = 0; j < 8; j++)
#pragma unroll
            for (int k = 0; k < 4; k++) acc[i][j][k] = 0.f;

    const int NC = K / KT;

    auto load_tile = [&](int c, int buf) {
        const float* Ag = A  + (size_t)row0 * K + c * KT;
        const float* Bg = Bt + (size_t)col0 * K + c * KT;
        const uint32_t ab = sbase + (uint32_t)buf * 2 * MATB;
        const uint32_t bb = ab + MATB;
#pragma unroll
        for (int i = 0; i < 4; i++) {
            int id = tid + i * 256;
            int r = id >> 3, c4 = id & 7;
            uint32_t off = (uint32_t)(r * PAD + c4 * 4) * 4;
            cp_async16(ab + off, Ag + (size_t)r * K + c4 * 4);
            cp_async16(bb + off, Bg + (size_t)r * K + c4 * 4);
        }
        cp_commit();
    };

    load_tile(0, 0);

    // ldmatrix per-lane source rows/cols (fp32 units)
    const int arow = wm * 32 + (lane & 15);
    const int acol = (lane >> 4) << 2;
    const int brow = wn * 64 + ((lane >> 4) << 3) + (lane & 7);
    const int bcol = ((lane >> 3) & 1) << 2;

    for (int c = 0; c < NC; c++) {
        const int buf = c & 1;
        cp_wait<0>();
        __syncthreads();
        if (c + 1 < NC) load_tile(c + 1, buf ^ 1);

        const uint32_t au = sbase + (uint32_t)buf * 2 * MATB;
        const uint32_t bu = au + MATB;

#pragma unroll
        for (int ks = 0; ks < 4; ks++) {
            const int ck = ks * 8;
            uint32_t afr[2][4], bfr[4][4];
#pragma unroll
            for (int mi = 0; mi < 2; mi++) {
                ldsm_x4u(afr[mi], au + (uint32_t)(((arow + mi * 16) * PAD) + ck + acol) * 4);
#pragma unroll
                for (int r = 0; r < 4; r++) afr[mi][r] = tf32r_u(afr[mi][r]);
            }
#pragma unroll
            for (int nip = 0; nip < 4; nip++)
                ldsm_x4u(bfr[nip], bu + (uint32_t)(((brow + nip * 16) * PAD) + ck + bcol) * 4);
#pragma unroll
            for (int mi = 0; mi < 2; mi++)
#pragma unroll
                for (int ni = 0; ni < 8; ni++)
                    mma_tf32u(acc[mi][ni], afr[mi],
                              bfr[ni >> 1][(ni & 1) * 2], bfr[ni >> 1][(ni & 1) * 2 + 1]);
        }
    }

    const int qr = lane >> 2;
    const int qc = (lane & 3) * 2;
#pragma unroll
    for (int mi = 0; mi < 2; mi++) {
#pragma unroll
        for (int ni = 0; ni < 8; ni++) {
            int col = col0 + wn * 64 + ni * 8 + qc;
            float b0 = bias[col], b1 = bias[col + 1];
            int r0 = row0 + wm * 32 + mi * 16 + qr;
            float v0 = acc[mi][ni][0] + b0;
            float v1 = acc[mi][ni][1] + b1;
            float v2 = acc[mi][ni][2] + b0;
            float v3 = acc[mi][ni][3] + b1;
            if (relu) {
                v0 = fmaxf(v0, 0.f); v1 = fmaxf(v1, 0.f);
                v2 = fmaxf(v2, 0.f); v3 = fmaxf(v3, 0.f);
            }
            if (round_out) {
                v0 = tf32r(v0); v1 = tf32r(v1);
                v2 = tf32r(v2); v3 = tf32r(v3);
            }
            *(float2*)(C + (size_t)r0 * N + col)       = make_float2(v0, v1);
            *(float2*)(C + (size_t)(r0 + 8) * N + col) = make_float2(v2, v3);
        }
    }
}

// ---------------- fused flash attention (R11 version, known-good) ----------------
#define QT 64
#define KTL 128
#define QS 68
#define VS 132
#define FSMEM ((QT*QS + KTL*QS + 64*VS + 256) * 4)   // 87040 B

__global__ void __launch_bounds__(256, 2)
flash_kernel(const float* __restrict__ Qg, const float* __restrict__ Kg,
             const float* __restrict__ Vtg, const int* __restrict__ mask,
             float* __restrict__ ctx)
{
    extern __shared__ float sf[];
    float* Qs  = sf;                   // 64 x QS
    float* Ks  = Qs + QT * QS;         // 128 x QS  (K tile; P aliases)
    float* Vts = Ks + KTL * QS;        // 64 x VS
    float* Ps  = Ks;                   // alias
    float* tmpM = Vts + 64 * VS;       // 128
    float* tmpS = tmpM + 128;          // 128

    const int tid = threadIdx.x;
    const int wid = tid >> 5, lane = tid & 31;
    const int wm = wid & 3, wn = wid >> 2;
    const int qr = lane >> 2, qc = lane & 3;
    const int bh = blockIdx.y, b = bh >> 4, h = bh & 15;
    const int q0 = blockIdx.x * QT;

    const uint32_t qs_u = smem_u32(Qs), ks_u = smem_u32(Ks), vs_u = smem_u32(Vts);
    const uint32_t ps_u = ks_u;

    const int arow = wm * 16 + (lane & 15);
    const int acol = (lane >> 4) << 2;
    const int brow = ((lane >> 4) << 3) + (lane & 7);
    const int bcol = ((lane >> 3) & 1) << 2;

    // load Q tile (once)
#pragma unroll
    for (int i = 0; i < 4; i++) {
        int id = tid + i * 256;
        int r = id >> 4, ch = id & 15;
        cp_async16(qs_u + (uint32_t)(r * QS + ch * 4) * 4,
                   Qg + (size_t)(b * Sq + q0 + r) * Eq + h * 64 + ch * 4);
    }
    cp_commit();

    float m0 = -INFINITY, m1 = -INFINITY;
    float l0 = 0.f, l1 = 0.f;
    float acc_o[4][4] = {};

    const int rloc = wm * 16 + qr;

    for (int kt = 0; kt < Sq / KTL; kt++) {
#pragma unroll
        for (int i = 0; i < 8; i++) {
            int id = tid + i * 256;
            int r = id >> 4, ch = id & 15;
            cp_async16(ks_u + (uint32_t)(r * QS + ch * 4) * 4,
                       Kg + (size_t)(b * Sq + kt * KTL + r) * Eq + h * 64 + ch * 4);
        }
#pragma unroll
        for (int i = 0; i < 8; i++) {
            int id = tid + i * 256;
            int r = id >> 5, ch = id & 31;
            cp_async16(vs_u + (uint32_t)(r * VS + ch * 4) * 4,
                       Vtg + (size_t)(b * Eq + h * 64 + r) * Sq + kt * KTL + ch * 4);
        }
        cp_commit();
        cp_wait<0>();
        __syncthreads();

        // S = Q @ K^T
        float acc_s[8][4];
#pragma unroll
        for (int ni = 0; ni < 8; ni++)
#pragma unroll
            for (int k = 0; k < 4; k++) acc_s[ni][k] = 0.f;
#pragma unroll
        for (int ks = 0; ks < 8; ks++) {
            const int ck = ks * 8;
            uint32_t afr[4];
            ldsm_x4u(afr, qs_u + (uint32_t)(arow * QS + ck + acol) * 4);
#pragma unroll
            for (int nip = 0; nip < 4; nip++) {
                uint32_t bfr[4];
                ldsm_x4u(bfr, ks_u + (uint32_t)((wn * 64 + nip * 16 + brow) * QS + ck + bcol) * 4);
                mma_tf32u(acc_s[nip * 2],     afr, bfr[0], bfr[1]);
                mma_tf32u(acc_s[nip * 2 + 1], afr, bfr[2], bfr[3]);
            }
        }

        // mask + rsqrt, row max
        float mr0 = -INFINITY, mr1 = -INFINITY;
#pragma unroll
        for (int ni = 0; ni < 8; ni++) {
            int colg = kt * KTL + wn * 64 + ni * 8 + qc * 2;
            int mk0 = mask[b * Sq + colg], mk1 = mask[b * Sq + colg + 1];
            float s0 = mk0 ? rsqrtf(acc_s[ni][0]) : -INFINITY;
            float s1 = mk1 ? rsqrtf(acc_s[ni][1]) : -INFINITY;
            float s2 = mk0 ? rsqrtf(acc_s[ni][2]) : -INFINITY;
            float s3 = mk1 ? rsqrtf(acc_s[ni][3]) : -INFINITY;
            acc_s[ni][0] = s0; acc_s[ni][1] = s1; acc_s[ni][2] = s2; acc_s[ni][3] = s3;
            mr0 = fmaxf(mr0, fmaxf(s0, s1));
            mr1 = fmaxf(mr1, fmaxf(s2, s3));
        }
#pragma unroll
        for (int o = 1; o < 4; o <<= 1) {
            mr0 = fmaxf(mr0, __shfl_xor_sync(0xffffffffu, mr0, o));
            mr1 = fmaxf(mr1, __shfl_xor_sync(0xffffffffu, mr1, o));
        }
        if (qc == 0) { tmpM[wn * 64 + rloc] = mr0; tmpM[wn * 64 + rloc + 8] = mr1; }
        __syncthreads();
        float mt0 = fmaxf(tmpM[rloc],     tmpM[64 + rloc]);
        float mt1 = fmaxf(tmpM[rloc + 8], tmpM[64 + rloc + 8]);
        float mn0 = fmaxf(m0, mt0), mn1 = fmaxf(m1, mt1);
        float mn0s = (mn0 == -INFINITY) ? 0.f : mn0;
        float mn1s = (mn1 == -INFINITY) ? 0.f : mn1;
        float sc0 = __expf(m0 - mn0s);
        float sc1 = __expf(m1 - mn1s);
        m0 = mn0; m1 = mn1;

        // exp, row sum, store P (tf32-rounded) into dead K region
        float sr0 = 0.f, sr1 = 0.f;
#pragma unroll
        for (int ni = 0; ni < 8; ni++) {
            float p0 = __expf(acc_s[ni][0] - mn0s);
            float p1 = __expf(acc_s[ni][1] - mn0s);
            float p2 = __expf(acc_s[ni][2] - mn1s);
            float p3 = __expf(acc_s[ni][3] - mn1s);
            sr0 += p0 + p1; sr1 += p2 + p3;
            int colp = wn * 64 + ni * 8 + qc * 2;
            Ps[rloc * VS + colp]           = tf32r(p0);
            Ps[rloc * VS + colp + 1]       = tf32r(p1);
            Ps[(rloc + 8) * VS + colp]     = tf32r(p2);
            Ps[(rloc + 8) * VS + colp + 1] = tf32r(p3);
        }
#pragma unroll
        for (int o = 1; o < 4; o <<= 1) {
            sr0 += __shfl_xor_sync(0xffffffffu, sr0, o);
            sr1 += __shfl_xor_sync(0xffffffffu, sr1, o);
        }
        if (qc == 0) { tmpS[wn * 64 + rloc] = sr0; tmpS[wn * 64 + rloc + 8] = sr1; }
        __syncthreads();
        l0 = l0 * sc0 + tmpS[rloc]     + tmpS[64 + rloc];
        l1 = l1 * sc1 + tmpS[rloc + 8] + tmpS[64 + rloc + 8];

#pragma unroll
        for (int ni = 0; ni < 4; ni++) {
            acc_o[ni][0] *= sc0; acc_o[ni][1] *= sc0;
            acc_o[ni][2] *= sc1; acc_o[ni][3] *= sc1;
        }

        // O += P @ V
#pragma unroll
        for (int ks = 0; ks < 16; ks++) {
            const int ck = ks * 8;
            uint32_t afr[4];
            ldsm_x4u(afr, ps_u + (uint32_t)(arow * VS + ck + acol) * 4);
#pragma unroll
            for (int nip = 0; nip < 2; nip++) {
                uint32_t bfr[4];
                ldsm_x4u(bfr, vs_u + (uint32_t)((wn * 32 + nip * 16 + brow) * VS + ck + bcol) * 4);
                mma_tf32u(acc_o[nip * 2],     afr, bfr[0], bfr[1]);
                mma_tf32u(acc_o[nip * 2 + 1], afr, bfr[2], bfr[3]);
            }
        }
        __syncthreads();
    }

    // epilogue
    float inv0 = 1.f / l0, inv1 = 1.f / l1;
#pragma unroll
    for (int ni = 0; ni < 4; ni++) {
        int col = h * 64 + wn * 32 + ni * 8 + qc * 2;
        size_t r = (size_t)(b * Sq + q0 + rloc);
        *(float2*)(ctx + r * Eq + col) =
            make_float2(tf32r(acc_o[ni][0] * inv0), tf32r(acc_o[ni][1] * inv0));
        *(float2*)(ctx + (r + 8) * Eq + col) =
            make_float2(tf32r(acc_o[ni][2] * inv1), tf32r(acc_o[ni][3] * inv1));
    }
}

// ---------------- out = LayerNorm(A + R) ----------------
__global__ void __launch_bounds__(256)
add_ln_kernel(const float* __restrict__ A, const float* __restrict__ R,
              const float* __restrict__ g, const float* __restrict__ be,
              float* __restrict__ out)
{
    const size_t row = blockIdx.x;
    const int tid = threadIdx.x;
    const int lane = tid & 31, warp = tid >> 5;
    __shared__ float red[8];
    const float* pa = A + row * Eq;
    const float* pr = R + row * Eq;

    float v[4];
    float s = 0.f;
#pragma unroll
    for (int i = 0; i < 4; i++) {
        v[i] = pa[tid + i * 256] + pr[tid + i * 256];
        s += v[i];
    }
#pragma unroll
    for (int o = 16; o; o >>= 1) s += __shfl_xor_sync(0xffffffffu, s, o);
    if (lane == 0) red[warp] = s;
    __syncthreads();
    if (tid == 0) {
        float t = 0.f;
#pragma unroll
        for (int i = 0; i < 8; i++) t += red[i];
        red[0] = t;
    }
    __syncthreads();
    const float mean = red[0] * (1.f / Eq);
    __syncthreads();

    float s2 = 0.f;
#pragma unroll
    for (int i = 0; i < 4; i++) {
        float d = v[i] - mean;
        s2 += d * d;
    }
#pragma unroll
    for (int o = 16; o; o >>= 1) s2 += __shfl_xor_sync(0xffffffffu, s2, o);
    if (lane == 0) red[warp] = s2;
    __syncthreads();
    if (tid == 0) {
        float t = 0.f;
#pragma unroll
        for (int i = 0; i < 8; i++) t += red[i];
        red[0] = t;
    }
    __syncthreads();
    const float inv = rsqrtf(red[0] * (1.f / Eq) + LN_EPS);

#pragma unroll
    for (int i = 0; i < 4; i++) {
        int c = tid + i * 256;
        out[row * Eq + c] = (v[i] - mean) * inv * g[c] + be[c];
    }
}

// ---------------- host launch ----------------
extern "C" void kernel_launch(void* const* d_in, const int* in_sizes, int n_in,
                              void* d_out, int out_size)
{
    const float* value = (const float*)d_in[0];
    const float* key   = (const float*)d_in[1];
    const float* query = (const float*)d_in[2];
    const int*   mask  = (const int*)d_in[3];
    const float* Wv = (const float*)d_in[4];
    const float* bv = (const float*)d_in[5];
    const float* Wk = (const float*)d_in[6];
    const float* bk = (const float*)d_in[7];
    const float* Wq = (const float*)d_in[8];
    const float* bq = (const float*)d_in[9];
    const float* Wo = (const float*)d_in[10];
    const float* bo = (const float*)d_in[11];
    const float* W1 = (const float*)d_in[12];
    const float* b1 = (const float*)d_in[13];
    const float* W2 = (const float*)d_in[14];
    const float* b2 = (const float*)d_in[15];
    const float* g1  = (const float*)d_in[16];
    const float* be1 = (const float*)d_in[17];
    const float* g2  = (const float*)d_in[18];
    const float* be2 = (const float*)d_in[19];
    float* out = (float*)d_out;

    float *pV, *pK, *pQ, *pVt, *pCtx, *pAo, *pX, *pH, *pFf;
    float *pWvt, *pWkt, *pWqt, *pWot, *pW1t, *pW2t;
    cudaGetSymbolAddress((void**)&pV,   g_V);
    cudaGetSymbolAddress((void**)&pK,   g_K);
    cudaGetSymbolAddress((void**)&pQ,   g_Q);
    cudaGetSymbolAddress((void**)&pVt,  g_Vt);
    cudaGetSymbolAddress((void**)&pCtx, g_ctx);
    cudaGetSymbolAddress((void**)&pAo,  g_ao);
    cudaGetSymbolAddress((void**)&pX,   g_x);
    cudaGetSymbolAddress((void**)&pH,   g_h);
    cudaGetSymbolAddress((void**)&pFf,  g_ff);
    cudaGetSymbolAddress((void**)&pWvt, g_Wvt);
    cudaGetSymbolAddress((void**)&pWkt, g_Wkt);
    cudaGetSymbolAddress((void**)&pWqt, g_Wqt);
    cudaGetSymbolAddress((void**)&pWot, g_Wot);
    cudaGetSymbolAddress((void**)&pW1t, g_W1t);
    cudaGetSymbolAddress((void**)&pW2t, g_W2t);

    cudaFuncSetAttribute(gemm_tf32, cudaFuncAttributeMaxDynamicSharedMemorySize, GSMEM);
    cudaFuncSetAttribute(flash_kernel, cudaFuncAttributeMaxDynamicSharedMemorySize, FSMEM);

    const int M = Bq * Sq;  // 4096
    dim3 blk(256);

    // weight transpose + tf32 rounding
    transpose_tf32_kernel<<<dim3(Eq / 32, Eq / 32), blk>>>(Wv, pWvt, Eq, Eq);
    transpose_tf32_kernel<<<dim3(Eq / 32, Eq / 32), blk>>>(Wk, pWkt, Eq, Eq);
    transpose_tf32_kernel<<<dim3(Eq / 32, Eq / 32), blk>>>(Wq, pWqt, Eq, Eq);
    transpose_tf32_kernel<<<dim3(Eq / 32, Eq / 32), blk>>>(Wo, pWot, Eq, Eq);
    transpose_tf32_kernel<<<dim3(FFq / 32, Eq / 32), blk>>>(W1, pW1t, Eq, FFq);
    transpose_tf32_kernel<<<dim3(Eq / 32, FFq / 32), blk>>>(W2, pW2t, FFq, Eq);

    // QKV projections: raw inputs, A-fragment rounding in-kernel; rounded outputs for flash
    dim3 grid_e(Eq / 128, M / 128);
    gemm_tf32<<<grid_e, blk, GSMEM>>>(value, pWvt, bv, pV, M, Eq, Eq, 0, 1);
    gemm_tf32<<<grid_e, blk, GSMEM>>>(key,   pWkt, bk, pK, M, Eq, Eq, 0, 1);
    gemm_tf32<<<grid_e, blk, GSMEM>>>(query, pWqt, bq, pQ, M, Eq, Eq, 0, 1);

    // V transpose per batch
    vtrans_kernel<<<dim3(Sq / 32, Eq / 32, Bq), blk>>>(pV, pVt);

    // fused flash attention -> ctx (tf32-rounded)
    flash_kernel<<<dim3(Sq / QT, Bq * Hh), blk, FSMEM>>>(pQ, pK, pVt, mask, pCtx);

    // output projection (ctx rounded; fragment round idempotent)
    gemm_tf32<<<grid_e, blk, GSMEM>>>(pCtx, pWot, bo, pAo, M, Eq, Eq, 0, 0);

    // x = LN(attn_out + query)
    add_ln_kernel<<<M, blk>>>(pAo, query, g1, be1, pX);

    // FFN1: reads raw x, fragment-rounds; output raw (FFN2 fragment-rounds)
    dim3 grid_ff1(FFq / 128, M / 128);
    gemm_tf32<<<grid_ff1, blk, GSMEM>>>(pX, pW1t, b1, pH, M, Eq, FFq, 1, 0);

    // FFN2
    dim3 grid_ff2(Eq / 128, M / 128);
    gemm_tf32<<<grid_ff2, blk, GSMEM>>>(pH, pW2t, b2, pFf, M, FFq, Eq, 0, 0);

    // out = LN(ff + x)
    add_ln_kernel<<<M, blk>>>(pFf, pX, g2, be2, out);
}

// round 15
// speedup vs baseline: 1.0246x; 1.0246x over previous
#include <cuda_runtime.h>
#include <math.h>
#include <stdint.h>

// ---------------- problem dims ----------------
#define Bq 4
#define Sq 1024
#define Eq 1024
#define Hh 16
#define Dd 64
#define FFq 4096
#define LN_EPS 1e-5f

// ---------------- scratch (device globals) ----------------
__device__ float g_V[Bq * Sq * Eq];
__device__ float g_K[Bq * Sq * Eq];
__device__ float g_Q[Bq * Sq * Eq];
__device__ float g_Vt[Bq * Sq * Eq];
__device__ float g_ctx[Bq * Sq * Eq];
__device__ float g_ao[Bq * Sq * Eq];
__device__ float g_x[Bq * Sq * Eq];
__device__ float g_xr[Bq * Sq * Eq];
__device__ float g_h[(size_t)Bq * Sq * FFq];
__device__ float g_ff[Bq * Sq * Eq];
__device__ float g_vr[Bq * Sq * Eq];
__device__ float g_kr[Bq * Sq * Eq];
__device__ float g_qr[Bq * Sq * Eq];
__device__ float g_Wvt[Eq * Eq];
__device__ float g_Wkt[Eq * Eq];
__device__ float g_Wqt[Eq * Eq];
__device__ float g_Wot[Eq * Eq];
__device__ float g_W1t[(size_t)Eq * FFq];
__device__ float g_W2t[(size_t)Eq * FFq];

// ---------------- PTX helpers ----------------
__device__ __forceinline__ uint32_t smem_u32(const void* p) {
    uint32_t a;
    asm("{ .reg .u64 t; cvta.to.shared.u64 t, %1; cvt.u32.u64 %0, t; }" : "=r"(a) : "l"(p));
    return a;
}
__device__ __forceinline__ void cp_async16(uint32_t dst, const void* src) {
    asm volatile("cp.async.ca.shared.global [%0], [%1], 16;" :: "r"(dst), "l"(src));
}
__device__ __forceinline__ void cp_commit() { asm volatile("cp.async.commit_group;"); }
template <int N>
__device__ __forceinline__ void cp_wait() { asm volatile("cp.async.wait_group %0;" :: "n"(N)); }

__device__ __forceinline__ float tf32r(float x) {
    uint32_t u;
    asm("cvt.rna.tf32.f32 %0, %1;" : "=r"(u) : "f"(x));
    return __uint_as_float(u);
}
__device__ __forceinline__ void ldsm_x4u(uint32_t* r, uint32_t addr) {
    asm volatile("ldmatrix.sync.aligned.m8n8.x4.shared.b16 {%0,%1,%2,%3}, [%4];"
        : "=r"(r[0]), "=r"(r[1]), "=r"(r[2]), "=r"(r[3]) : "r"(addr));
}
__device__ __forceinline__ void mma_tf32u(float* c, const uint32_t* a, uint32_t b0, uint32_t b1) {
    asm volatile(
        "mma.sync.aligned.m16n8k8.row.col.f32.tf32.tf32.f32 "
        "{%0,%1,%2,%3}, {%4,%5,%6,%7}, {%8,%9}, {%0,%1,%2,%3};"
        : "+f"(c[0]), "+f"(c[1]), "+f"(c[2]), "+f"(c[3])
        : "r"(a[0]), "r"(a[1]), "r"(a[2]), "r"(a[3]), "r"(b0), "r"(b1));
}

// ---------------- tf32 rounding pass ----------------
__global__ void __launch_bounds__(256)
round_tf32_kernel(const float* __restrict__ in, float* __restrict__ out, int n4)
{
    int i = blockIdx.x * 256 + threadIdx.x;
    if (i >= n4) return;
    float4 v = ((const float4*)in)[i];
    v.x = tf32r(v.x); v.y = tf32r(v.y); v.z = tf32r(v.z); v.w = tf32r(v.w);
    ((float4*)out)[i] = v;
}

// ---------------- W[K,N] fp32 -> Wt[N,K] tf32-rounded ----------------
__global__ void __launch_bounds__(256)
transpose_tf32_kernel(const float* __restrict__ W, float* __restrict__ Wt, int K, int N)
{
    __shared__ float t[32][33];
    const int k0 = blockIdx.y * 32, n0 = blockIdx.x * 32;
    const int tx = threadIdx.x & 31, ty = threadIdx.x >> 5;
#pragma unroll
    for (int i = 0; i < 32; i += 8)
        t[ty + i][tx] = W[(size_t)(k0 + ty + i) * N + n0 + tx];
    __syncthreads();
#pragma unroll
    for (int i = 0; i < 32; i += 8)
        Wt[(size_t)(n0 + ty + i) * K + k0 + tx] = tf32r(t[tx][ty + i]);
}

// ---------------- per-batch transpose: Vt[(b*E+c)][k] = V[(b*S+k)][c] ----------------
__global__ void __launch_bounds__(256)
vtrans_kernel(const float* __restrict__ V, float* __restrict__ Vt)
{
    __shared__ float t[32][33];
    const int b = blockIdx.z;
    const int k0 = blockIdx.x * 32, c0 = blockIdx.y * 32;
    const int tx = threadIdx.x & 31, ty = threadIdx.x >> 5;
#pragma unroll
    for (int i = 0; i < 32; i += 8)
        t[ty + i][tx] = V[(size_t)(b * Sq + k0 + ty + i) * Eq + c0 + tx];
    __syncthreads();
#pragma unroll
    for (int i = 0; i < 32; i += 8)
        Vt[(size_t)(b * Eq + c0 + ty + i) * Sq + k0 + tx] = t[tx][ty + i];
}

// ---------------- tf32 MMA GEMM body (R11 config, known-good) ----------------
#define KT 32
#define PAD 36
#define GSMEM (2 * 2 * 128 * PAD * 4)   // 73728 B -> 2 CTAs/SM

__device__ __forceinline__ void gemm_body(
    const float* __restrict__ A, const float* __restrict__ Bt,
    const float* __restrict__ bias, float* __restrict__ C,
    int K, int N, int relu, int round_out, int row0, int col0, float* sm)
{
    const int tid = threadIdx.x;
    const int wid = tid >> 5, lane = tid & 31;
    const int wm = wid & 3, wn = wid >> 2;

    const uint32_t sbase = smem_u32(sm);
    const uint32_t MATB = 128 * PAD * 4;

    float acc[2][8][4];
#pragma unroll
    for (int i = 0; i < 2; i++)
#pragma unroll
        for (int j = 0; j < 8; j++)
#pragma unroll
            for (int k = 0; k < 4; k++) acc[i][j][k] = 0.f;

    const int NC = K / KT;

    auto load_tile = [&](int c, int buf) {
        const float* Ag = A  + (size_t)row0 * K + c * KT;
        const float* Bg = Bt + (size_t)col0 * K + c * KT;
        const uint32_t ab = sbase + (uint32_t)buf * 2 * MATB;
        const uint32_t bb = ab + MATB;
#pragma unroll
        for (int i = 0; i < 4; i++) {
            int id = tid + i * 256;
            int r = id >> 3, c4 = id & 7;
            uint32_t off = (uint32_t)(r * PAD + c4 * 4) * 4;
            cp_async16(ab + off, Ag + (size_t)r * K + c4 * 4);
            cp_async16(bb + off, Bg + (size_t)r * K + c4 * 4);
        }
        cp_commit();
    };

    load_tile(0, 0);

    const int arow = wm * 32 + (lane & 15);
    const int acol = (lane >> 4) << 2;
    const int brow = wn * 64 + ((lane >> 4) << 3) + (lane & 7);
    const int bcol = ((lane >> 3) & 1) << 2;

    for (int c = 0; c < NC; c++) {
        const int buf = c & 1;
        cp_wait<0>();
        __syncthreads();
        if (c + 1 < NC) load_tile(c + 1, buf ^ 1);

        const uint32_t au = sbase + (uint32_t)buf * 2 * MATB;
        const uint32_t bu = au + MATB;

#pragma unroll
        for (int ks = 0; ks < 4; ks++) {
            const int ck = ks * 8;
            uint32_t afr[2][4], bfr[4][4];
#pragma unroll
            for (int mi = 0; mi < 2; mi++)
                ldsm_x4u(afr[mi], au + (uint32_t)(((arow + mi * 16) * PAD) + ck + acol) * 4);
#pragma unroll
            for (int nip = 0; nip < 4; nip++)
                ldsm_x4u(bfr[nip], bu + (uint32_t)(((brow + nip * 16) * PAD) + ck + bcol) * 4);
#pragma unroll
            for (int mi = 0; mi < 2; mi++)
#pragma unroll
                for (int ni = 0; ni < 8; ni++)
                    mma_tf32u(acc[mi][ni], afr[mi],
                              bfr[ni >> 1][(ni & 1) * 2], bfr[ni >> 1][(ni & 1) * 2 + 1]);
        }
    }

    const int qr = lane >> 2;
    const int qc = (lane & 3) * 2;
#pragma unroll
    for (int mi = 0; mi < 2; mi++) {
#pragma unroll
        for (int ni = 0; ni < 8; ni++) {
            int col = col0 + wn * 64 + ni * 8 + qc;
            float b0 = bias[col], b1 = bias[col + 1];
            int r0 = row0 + wm * 32 + mi * 16 + qr;
            float v0 = acc[mi][ni][0] + b0;
            float v1 = acc[mi][ni][1] + b1;
            float v2 = acc[mi][ni][2] + b0;
            float v3 = acc[mi][ni][3] + b1;
            if (relu) {
                v0 = fmaxf(v0, 0.f); v1 = fmaxf(v1, 0.f);
                v2 = fmaxf(v2, 0.f); v3 = fmaxf(v3, 0.f);
            }
            if (round_out) {
                v0 = tf32r(v0); v1 = tf32r(v1);
                v2 = tf32r(v2); v3 = tf32r(v3);
            }
            *(float2*)(C + (size_t)r0 * N + col)       = make_float2(v0, v1);
            *(float2*)(C + (size_t)(r0 + 8) * N + col) = make_float2(v2, v3);
        }
    }
}

__global__ void __launch_bounds__(256)
gemm_tf32(const float* __restrict__ A, const float* __restrict__ Bt,
          const float* __restrict__ bias, float* __restrict__ C,
          int M, int K, int N, int relu, int round_out)
{
    extern __shared__ float sm[];
    gemm_body(A, Bt, bias, C, K, N, relu, round_out,
              blockIdx.y * 128, blockIdx.x * 128, sm);
}

// merged QKV: blockIdx.z selects (A, W, bias, C); per-CTA code identical
__global__ void __launch_bounds__(256)
gemm_tf32_qkv(const float* A0, const float* A1, const float* A2,
              const float* W0, const float* W1, const float* W2,
              const float* b0, const float* b1, const float* b2,
              float* C0, float* C1, float* C2,
              int M, int K, int N)
{
    extern __shared__ float sm[];
    const float *A, *W, *bb;
    float* C;
    if (blockIdx.z == 0)      { A = A0; W = W0; bb = b0; C = C0; }
    else if (blockIdx.z == 1) { A = A1; W = W1; bb = b1; C = C1; }
    else                      { A = A2; W = W2; bb = b2; C = C2; }
    gemm_body(A, W, bb, C, K, N, 0, 1, blockIdx.y * 128, blockIdx.x * 128, sm);
}

// ---------------- fused flash attention (R11 version, known-good) ----------------
#define QT 64
#define KTL 128
#define QS 68
#define VS 132
#define FSMEM ((QT*QS + KTL*QS + 64*VS + 256) * 4)   // 87040 B

__global__ void __launch_bounds__(256, 2)
flash_kernel(const float* __restrict__ Qg, const float* __restrict__ Kg,
             const float* __restrict__ Vtg, const int* __restrict__ mask,
             float* __restrict__ ctx)
{
    extern __shared__ float sf[];
    float* Qs  = sf;                   // 64 x QS
    float* Ks  = Qs + QT * QS;         // 128 x QS  (K tile; P aliases)
    float* Vts = Ks + KTL * QS;        // 64 x VS
    float* Ps  = Ks;                   // alias
    float* tmpM = Vts + 64 * VS;       // 128
    float* tmpS = tmpM + 128;          // 128

    const int tid = threadIdx.x;
    const int wid = tid >> 5, lane = tid & 31;
    const int wm = wid & 3, wn = wid >> 2;
    const int qr = lane >> 2, qc = lane & 3;
    const int bh = blockIdx.y, b = bh >> 4, h = bh & 15;
    const int q0 = blockIdx.x * QT;

    const uint32_t qs_u = smem_u32(Qs), ks_u = smem_u32(Ks), vs_u = smem_u32(Vts);
    const uint32_t ps_u = ks_u;

    const int arow = wm * 16 + (lane & 15);
    const int acol = (lane >> 4) << 2;
    const int brow = ((lane >> 4) << 3) + (lane & 7);
    const int bcol = ((lane >> 3) & 1) << 2;

    // load Q tile (once)
#pragma unroll
    for (int i = 0; i < 4; i++) {
        int id = tid + i * 256;
        int r = id >> 4, ch = id & 15;
        cp_async16(qs_u + (uint32_t)(r * QS + ch * 4) * 4,
                   Qg + (size_t)(b * Sq + q0 + r) * Eq + h * 64 + ch * 4);
    }
    cp_commit();

    float m0 = -INFINITY, m1 = -INFINITY;
    float l0 = 0.f, l1 = 0.f;
    float acc_o[4][4] = {};

    const int rloc = wm * 16 + qr;

    for (int kt = 0; kt < Sq / KTL; kt++) {
#pragma unroll
        for (int i = 0; i < 8; i++) {
            int id = tid + i * 256;
            int r = id >> 4, ch = id & 15;
            cp_async16(ks_u + (uint32_t)(r * QS + ch * 4) * 4,
                       Kg + (size_t)(b * Sq + kt * KTL + r) * Eq + h * 64 + ch * 4);
        }
#pragma unroll
        for (int i = 0; i < 8; i++) {
            int id = tid + i * 256;
            int r = id >> 5, ch = id & 31;
            cp_async16(vs_u + (uint32_t)(r * VS + ch * 4) * 4,
                       Vtg + (size_t)(b * Eq + h * 64 + r) * Sq + kt * KTL + ch * 4);
        }
        cp_commit();
        cp_wait<0>();
        __syncthreads();

        // S = Q @ K^T
        float acc_s[8][4];
#pragma unroll
        for (int ni = 0; ni < 8; ni++)
#pragma unroll
            for (int k = 0; k < 4; k++) acc_s[ni][k] = 0.f;
#pragma unroll
        for (int ks = 0; ks < 8; ks++) {
            const int ck = ks * 8;
            uint32_t afr[4];
            ldsm_x4u(afr, qs_u + (uint32_t)(arow * QS + ck + acol) * 4);
#pragma unroll
            for (int nip = 0; nip < 4; nip++) {
                uint32_t bfr[4];
                ldsm_x4u(bfr, ks_u + (uint32_t)((wn * 64 + nip * 16 + brow) * QS + ck + bcol) * 4);
                mma_tf32u(acc_s[nip * 2],     afr, bfr[0], bfr[1]);
                mma_tf32u(acc_s[nip * 2 + 1], afr, bfr[2], bfr[3]);
            }
        }

        // mask + rsqrt, row max
        float mr0 = -INFINITY, mr1 = -INFINITY;
#pragma unroll
        for (int ni = 0; ni < 8; ni++) {
            int colg = kt * KTL + wn * 64 + ni * 8 + qc * 2;
            int mk0 = mask[b * Sq + colg], mk1 = mask[b * Sq + colg + 1];
            float s0 = mk0 ? rsqrtf(acc_s[ni][0]) : -INFINITY;
            float s1 = mk1 ? rsqrtf(acc_s[ni][1]) : -INFINITY;
            float s2 = mk0 ? rsqrtf(acc_s[ni][2]) : -INFINITY;
            float s3 = mk1 ? rsqrtf(acc_s[ni][3]) : -INFINITY;
            acc_s[ni][0] = s0; acc_s[ni][1] = s1; acc_s[ni][2] = s2; acc_s[ni][3] = s3;
            mr0 = fmaxf(mr0, fmaxf(s0, s1));
            mr1 = fmaxf(mr1, fmaxf(s2, s3));
        }
#pragma unroll
        for (int o = 1; o < 4; o <<= 1) {
            mr0 = fmaxf(mr0, __shfl_xor_sync(0xffffffffu, mr0, o));
            mr1 = fmaxf(mr1, __shfl_xor_sync(0xffffffffu, mr1, o));
        }
        if (qc == 0) { tmpM[wn * 64 + rloc] = mr0; tmpM[wn * 64 + rloc + 8] = mr1; }
        __syncthreads();
        float mt0 = fmaxf(tmpM[rloc],     tmpM[64 + rloc]);
        float mt1 = fmaxf(tmpM[rloc + 8], tmpM[64 + rloc + 8]);
        float mn0 = fmaxf(m0, mt0), mn1 = fmaxf(m1, mt1);
        float mn0s = (mn0 == -INFINITY) ? 0.f : mn0;
        float mn1s = (mn1 == -INFINITY) ? 0.f : mn1;
        float sc0 = __expf(m0 - mn0s);
        float sc1 = __expf(m1 - mn1s);
        m0 = mn0; m1 = mn1;

        // exp, row sum, store P (tf32-rounded) into dead K region
        float sr0 = 0.f, sr1 = 0.f;
#pragma unroll
        for (int ni = 0; ni < 8; ni++) {
            float p0 = __expf(acc_s[ni][0] - mn0s);
            float p1 = __expf(acc_s[ni][1] - mn0s);
            float p2 = __expf(acc_s[ni][2] - mn1s);
            float p3 = __expf(acc_s[ni][3] - mn1s);
            sr0 += p0 + p1; sr1 += p2 + p3;
            int colp = wn * 64 + ni * 8 + qc * 2;
            Ps[rloc * VS + colp]           = tf32r(p0);
            Ps[rloc * VS + colp + 1]       = tf32r(p1);
            Ps[(rloc + 8) * VS + colp]     = tf32r(p2);
            Ps[(rloc + 8) * VS + colp + 1] = tf32r(p3);
        }
#pragma unroll
        for (int o = 1; o < 4; o <<= 1) {
            sr0 += __shfl_xor_sync(0xffffffffu, sr0, o);
            sr1 += __shfl_xor_sync(0xffffffffu, sr1, o);
        }
        if (qc == 0) { tmpS[wn * 64 + rloc] = sr0; tmpS[wn * 64 + rloc + 8] = sr1; }
        __syncthreads();
        l0 = l0 * sc0 + tmpS[rloc]     + tmpS[64 + rloc];
        l1 = l1 * sc1 + tmpS[rloc + 8] + tmpS[64 + rloc + 8];

#pragma unroll
        for (int ni = 0; ni < 4; ni++) {
            acc_o[ni][0] *= sc0; acc_o[ni][1] *= sc0;
            acc_o[ni][2] *= sc1; acc_o[ni][3] *= sc1;
        }

        // O += P @ V
#pragma unroll
        for (int ks = 0; ks < 16; ks++) {
            const int ck = ks * 8;
            uint32_t afr[4];
            ldsm_x4u(afr, ps_u + (uint32_t)(arow * VS + ck + acol) * 4);
#pragma unroll
            for (int nip = 0; nip < 2; nip++) {
                uint32_t bfr[4];
                ldsm_x4u(bfr, vs_u + (uint32_t)((wn * 32 + nip * 16 + brow) * VS + ck + bcol) * 4);
                mma_tf32u(acc_o[nip * 2],     afr, bfr[0], bfr[1]);
                mma_tf32u(acc_o[nip * 2 + 1], afr, bfr[2], bfr[3]);
            }
        }
        __syncthreads();
    }

    // epilogue
    float inv0 = 1.f / l0, inv1 = 1.f / l1;
#pragma unroll
    for (int ni = 0; ni < 4; ni++) {
        int col = h * 64 + wn * 32 + ni * 8 + qc * 2;
        size_t r = (size_t)(b * Sq + q0 + rloc);
        *(float2*)(ctx + r * Eq + col) =
            make_float2(tf32r(acc_o[ni][0] * inv0), tf32r(acc_o[ni][1] * inv0));
        *(float2*)(ctx + (r + 8) * Eq + col) =
            make_float2(tf32r(acc_o[ni][2] * inv1), tf32r(acc_o[ni][3] * inv1));
    }
}

// ---------------- out = LayerNorm(A + R); optional tf32-rounded copy ----------------
__global__ void __launch_bounds__(256)
add_ln_kernel(const float* __restrict__ A, const float* __restrict__ R,
              const float* __restrict__ g, const float* __restrict__ be,
              float* __restrict__ out, float* __restrict__ out_r)
{
    const size_t row = blockIdx.x;
    const int tid = threadIdx.x;
    const int lane = tid & 31, warp = tid >> 5;
    __shared__ float red[8];
    const float* pa = A + row * Eq;
    const float* pr = R + row * Eq;

    float v[4];
    float s = 0.f;
#pragma unroll
    for (int i = 0; i < 4; i++) {
        v[i] = pa[tid + i * 256] + pr[tid + i * 256];
        s += v[i];
    }
#pragma unroll
    for (int o = 16; o; o >>= 1) s += __shfl_xor_sync(0xffffffffu, s, o);
    if (lane == 0) red[warp] = s;
    __syncthreads();
    if (tid == 0) {
        float t = 0.f;
#pragma unroll
        for (int i = 0; i < 8; i++) t += red[i];
        red[0] = t;
    }
    __syncthreads();
    const float mean = red[0] * (1.f / Eq);
    __syncthreads();

    float s2 = 0.f;
#pragma unroll
    for (int i = 0; i < 4; i++) {
        float d = v[i] - mean;
        s2 += d * d;
    }
#pragma unroll
    for (int o = 16; o; o >>= 1) s2 += __shfl_xor_sync(0xffffffffu, s2, o);
    if (lane == 0) red[warp] = s2;
    __syncthreads();
    if (tid == 0) {
        float t = 0.f;
#pragma unroll
        for (int i = 0; i < 8; i++) t += red[i];
        red[0] = t;
    }
    __syncthreads();
    const float inv = rsqrtf(red[0] * (1.f / Eq) + LN_EPS);

#pragma unroll
    for (int i = 0; i < 4; i++) {
        int c = tid + i * 256;
        float o = (v[i] - mean) * inv * g[c] + be[c];
        out[row * Eq + c] = o;
        if (out_r) out_r[row * Eq + c] = tf32r(o);
    }
}

// ---------------- host launch ----------------
extern "C" void kernel_launch(void* const* d_in, const int* in_sizes, int n_in,
                              void* d_out, int out_size)
{
    const float* value = (const float*)d_in[0];
    const float* key   = (const float*)d_in[1];
    const float* query = (const float*)d_in[2];
    const int*   mask  = (const int*)d_in[3];
    const float* Wv = (const float*)d_in[4];
    const float* bv = (const float*)d_in[5];
    const float* Wk = (const float*)d_in[6];
    const float* bk = (const float*)d_in[7];
    const float* Wq = (const float*)d_in[8];
    const float* bq = (const float*)d_in[9];
    const float* Wo = (const float*)d_in[10];
    const float* bo = (const float*)d_in[11];
    const float* W1 = (const float*)d_in[12];
    const float* b1 = (const float*)d_in[13];
    const float* W2 = (const float*)d_in[14];
    const float* b2 = (const float*)d_in[15];
    const float* g1  = (const float*)d_in[16];
    const float* be1 = (const float*)d_in[17];
    const float* g2  = (const float*)d_in[18];
    const float* be2 = (const float*)d_in[19];
    float* out = (float*)d_out;

    float *pV, *pK, *pQ, *pVt, *pCtx, *pAo, *pX, *pXr, *pH, *pFf;
    float *pVr, *pKr, *pQr;
    float *pWvt, *pWkt, *pWqt, *pWot, *pW1t, *pW2t;
    cudaGetSymbolAddress((void**)&pV,   g_V);
    cudaGetSymbolAddress((void**)&pK,   g_K);
    cudaGetSymbolAddress((void**)&pQ,   g_Q);
    cudaGetSymbolAddress((void**)&pVt,  g_Vt);
    cudaGetSymbolAddress((void**)&pCtx, g_ctx);
    cudaGetSymbolAddress((void**)&pAo,  g_ao);
    cudaGetSymbolAddress((void**)&pX,   g_x);
    cudaGetSymbolAddress((void**)&pXr,  g_xr);
    cudaGetSymbolAddress((void**)&pH,   g_h);
    cudaGetSymbolAddress((void**)&pFf,  g_ff);
    cudaGetSymbolAddress((void**)&pVr,  g_vr);
    cudaGetSymbolAddress((void**)&pKr,  g_kr);
    cudaGetSymbolAddress((void**)&pQr,  g_qr);
    cudaGetSymbolAddress((void**)&pWvt, g_Wvt);
    cudaGetSymbolAddress((void**)&pWkt, g_Wkt);
    cudaGetSymbolAddress((void**)&pWqt, g_Wqt);
    cudaGetSymbolAddress((void**)&pWot, g_Wot);
    cudaGetSymbolAddress((void**)&pW1t, g_W1t);
    cudaGetSymbolAddress((void**)&pW2t, g_W2t);

    cudaFuncSetAttribute(gemm_tf32, cudaFuncAttributeMaxDynamicSharedMemorySize, GSMEM);
    cudaFuncSetAttribute(gemm_tf32_qkv, cudaFuncAttributeMaxDynamicSharedMemorySize, GSMEM);
    cudaFuncSetAttribute(flash_kernel, cudaFuncAttributeMaxDynamicSharedMemorySize, FSMEM);

    const int M = Bq * Sq;  // 4096
    dim3 blk(256);

    // weight transpose + tf32 rounding
    transpose_tf32_kernel<<<dim3(Eq / 32, Eq / 32), blk>>>(Wv, pWvt, Eq, Eq);
    transpose_tf32_kernel<<<dim3(Eq / 32, Eq / 32), blk>>>(Wk, pWkt, Eq, Eq);
    transpose_tf32_kernel<<<dim3(Eq / 32, Eq / 32), blk>>>(Wq, pWqt, Eq, Eq);
    transpose_tf32_kernel<<<dim3(Eq / 32, Eq / 32), blk>>>(Wo, pWot, Eq, Eq);
    transpose_tf32_kernel<<<dim3(FFq / 32, Eq / 32), blk>>>(W1, pW1t, Eq, FFq);
    transpose_tf32_kernel<<<dim3(Eq / 32, FFq / 32), blk>>>(W2, pW2t, FFq, Eq);

    // round activations feeding QKV GEMMs
    {
        int n4 = M * Eq / 4;
        round_tf32_kernel<<<(n4 + 255) / 256, 256>>>(value, pVr, n4);
        round_tf32_kernel<<<(n4 + 255) / 256, 256>>>(key,   pKr, n4);
        round_tf32_kernel<<<(n4 + 255) / 256, 256>>>(query, pQr, n4);
    }

    // QKV projections merged into ONE launch (z selects V/K/Q)
    dim3 grid_qkv(Eq / 128, M / 128, 3);
    gemm_tf32_qkv<<<grid_qkv, blk, GSMEM>>>(
        pVr, pKr, pQr, pWvt, pWkt, pWqt, bv, bk, bq, pV, pK, pQ, M, Eq, Eq);

    // V transpose per batch
    vtrans_kernel<<<dim3(Sq / 32, Eq / 32, Bq), blk>>>(pV, pVt);

    // fused flash attention -> ctx (tf32-rounded)
    flash_kernel<<<dim3(Sq / QT, Bq * Hh), blk, FSMEM>>>(pQ, pK, pVt, mask, pCtx);

    // output projection
    dim3 grid_e(Eq / 128, M / 128);
    gemm_tf32<<<grid_e, blk, GSMEM>>>(pCtx, pWot, bo, pAo, M, Eq, Eq, 0, 0);

    // x = LN(attn_out + query); tf32-rounded copy for FFN1
    add_ln_kernel<<<M, blk>>>(pAo, query, g1, be1, pX, pXr);

    // FFN1
    dim3 grid_ff1(FFq / 128, M / 128);
    gemm_tf32<<<grid_ff1, blk, GSMEM>>>(pXr, pW1t, b1, pH, M, Eq, FFq, 1, 1);

    // FFN2
    dim3 grid_ff2(Eq / 128, M / 128);
    gemm_tf32<<<grid_ff2, blk, GSMEM>>>(pH, pW2t, b2, pFf, M, FFq, Eq, 0, 0);

    // out = LN(ff + x)
    add_ln_kernel<<<M, blk>>>(pFf, pX, g2, be2, out, nullptr);
}

// round 16
// speedup vs baseline: 1.0414x; 1.0165x over previous
#include <cuda_runtime.h>
#include <math.h>
#include <stdint.h>

// ---------------- problem dims ----------------
#define Bq 4
#define Sq 1024
#define Eq 1024
#define Hh 16
#define Dd 64
#define FFq 4096
#define LN_EPS 1e-5f

// ---------------- scratch (device globals) ----------------
__device__ float g_V[Bq * Sq * Eq];
__device__ float g_K[Bq * Sq * Eq];
__device__ float g_Q[Bq * Sq * Eq];
__device__ float g_Vt[Bq * Sq * Eq];
__device__ float g_ctx[Bq * Sq * Eq];
__device__ float g_ao[Bq * Sq * Eq];
__device__ float g_x[Bq * Sq * Eq];
__device__ float g_xr[Bq * Sq * Eq];
__device__ float g_h[(size_t)Bq * Sq * FFq];
__device__ float g_ff[Bq * Sq * Eq];
__device__ float g_vr[Bq * Sq * Eq];
__device__ float g_kr[Bq * Sq * Eq];
__device__ float g_qr[Bq * Sq * Eq];
__device__ float g_Wvt[Eq * Eq];
__device__ float g_Wkt[Eq * Eq];
__device__ float g_Wqt[Eq * Eq];
__device__ float g_Wot[Eq * Eq];
__device__ float g_W1t[(size_t)Eq * FFq];
__device__ float g_W2t[(size_t)Eq * FFq];

// ---------------- PTX helpers ----------------
__device__ __forceinline__ uint32_t smem_u32(const void* p) {
    uint32_t a;
    asm("{ .reg .u64 t; cvta.to.shared.u64 t, %1; cvt.u32.u64 %0, t; }" : "=r"(a) : "l"(p));
    return a;
}
__device__ __forceinline__ void cp_async16(uint32_t dst, const void* src) {
    asm volatile("cp.async.ca.shared.global [%0], [%1], 16;" :: "r"(dst), "l"(src));
}
__device__ __forceinline__ void cp_commit() { asm volatile("cp.async.commit_group;"); }
template <int N>
__device__ __forceinline__ void cp_wait() { asm volatile("cp.async.wait_group %0;" :: "n"(N)); }

__device__ __forceinline__ float tf32r(float x) {
    uint32_t u;
    asm("cvt.rna.tf32.f32 %0, %1;" : "=r"(u) : "f"(x));
    return __uint_as_float(u);
}
__device__ __forceinline__ void ldsm_x4u(uint32_t* r, uint32_t addr) {
    asm volatile("ldmatrix.sync.aligned.m8n8.x4.shared.b16 {%0,%1,%2,%3}, [%4];"
        : "=r"(r[0]), "=r"(r[1]), "=r"(r[2]), "=r"(r[3]) : "r"(addr));
}
__device__ __forceinline__ void mma_tf32u(float* c, const uint32_t* a, uint32_t b0, uint32_t b1) {
    asm volatile(
        "mma.sync.aligned.m16n8k8.row.col.f32.tf32.tf32.f32 "
        "{%0,%1,%2,%3}, {%4,%5,%6,%7}, {%8,%9}, {%0,%1,%2,%3};"
        : "+f"(c[0]), "+f"(c[1]), "+f"(c[2]), "+f"(c[3])
        : "r"(a[0]), "r"(a[1]), "r"(a[2]), "r"(a[3]), "r"(b0), "r"(b1));
}

// ---------------- merged prep: 6 transposes + 3 round passes in ONE launch ----------------
// blocks [0,1024)Wv [1024,2048)Wk [2048,3072)Wq [3072,4096)Wo
//        [4096,8192)W1 [8192,12288)W2 [12288,24576) rounds (V,K,Q)
#define PREP_BLOCKS 24576

__device__ __forceinline__ void transpose_body(
    const float* __restrict__ W, float* __restrict__ Wt,
    int K, int N, int k0, int n0)
{
    __shared__ float t[32][33];
    const int tx = threadIdx.x & 31, ty = threadIdx.x >> 5;
#pragma unroll
    for (int i = 0; i < 32; i += 8)
        t[ty + i][tx] = W[(size_t)(k0 + ty + i) * N + n0 + tx];
    __syncthreads();
#pragma unroll
    for (int i = 0; i < 32; i += 8)
        Wt[(size_t)(n0 + ty + i) * K + k0 + tx] = tf32r(t[tx][ty + i]);
}

__global__ void __launch_bounds__(256)
prep_kernel(const float* __restrict__ Wv, const float* __restrict__ Wk,
            const float* __restrict__ Wq, const float* __restrict__ Wo,
            const float* __restrict__ W1, const float* __restrict__ W2,
            float* __restrict__ Wvt, float* __restrict__ Wkt,
            float* __restrict__ Wqt, float* __restrict__ Wot,
            float* __restrict__ W1t, float* __restrict__ W2t,
            const float* __restrict__ value, const float* __restrict__ key,
            const float* __restrict__ query,
            float* __restrict__ vr, float* __restrict__ kr, float* __restrict__ qr)
{
    const int b = blockIdx.x;
    if (b < 12288) {
        const float* W; float* Wt; int K, N, base;
        if (b < 1024)      { W = Wv; Wt = Wvt; K = Eq;  N = Eq;  base = 0; }
        else if (b < 2048) { W = Wk; Wt = Wkt; K = Eq;  N = Eq;  base = 1024; }
        else if (b < 3072) { W = Wq; Wt = Wqt; K = Eq;  N = Eq;  base = 2048; }
        else if (b < 4096) { W = Wo; Wt = Wot; K = Eq;  N = Eq;  base = 3072; }
        else if (b < 8192) { W = W1; Wt = W1t; K = Eq;  N = FFq; base = 4096; }
        else               { W = W2; Wt = W2t; K = FFq; N = Eq;  base = 8192; }
        const int lb = b - base;
        const int nbc = N / 32;
        transpose_body(W, Wt, K, N, (lb / nbc) * 32, (lb % nbc) * 32);
    } else {
        const int lb = b - 12288;
        const int which = lb / 4096;
        const float* in; float* out;
        if (which == 0)      { in = value; out = vr; }
        else if (which == 1) { in = key;   out = kr; }
        else                 { in = query; out = qr; }
        const int i = (lb % 4096) * 256 + threadIdx.x;   // 4096*256 = exactly M*Eq/4
        float4 v = ((const float4*)in)[i];
        v.x = tf32r(v.x); v.y = tf32r(v.y); v.z = tf32r(v.z); v.w = tf32r(v.w);
        ((float4*)out)[i] = v;
    }
}

// ---------------- per-batch transpose: Vt[(b*E+c)][k] = V[(b*S+k)][c] ----------------
__global__ void __launch_bounds__(256)
vtrans_kernel(const float* __restrict__ V, float* __restrict__ Vt)
{
    __shared__ float t[32][33];
    const int b = blockIdx.z;
    const int k0 = blockIdx.x * 32, c0 = blockIdx.y * 32;
    const int tx = threadIdx.x & 31, ty = threadIdx.x >> 5;
#pragma unroll
    for (int i = 0; i < 32; i += 8)
        t[ty + i][tx] = V[(size_t)(b * Sq + k0 + ty + i) * Eq + c0 + tx];
    __syncthreads();
#pragma unroll
    for (int i = 0; i < 32; i += 8)
        Vt[(size_t)(b * Eq + c0 + ty + i) * Sq + k0 + tx] = t[tx][ty + i];
}

// ---------------- tf32 MMA GEMM body (R11 config, known-good) ----------------
#define KT 32
#define PAD 36
#define GSMEM (2 * 2 * 128 * PAD * 4)   // 73728 B -> 2 CTAs/SM

__device__ __forceinline__ void gemm_body(
    const float* __restrict__ A, const float* __restrict__ Bt,
    const float* __restrict__ bias, float* __restrict__ C,
    int K, int N, int relu, int round_out, int row0, int col0, float* sm)
{
    const int tid = threadIdx.x;
    const int wid = tid >> 5, lane = tid & 31;
    const int wm = wid & 3, wn = wid >> 2;

    const uint32_t sbase = smem_u32(sm);
    const uint32_t MATB = 128 * PAD * 4;

    float acc[2][8][4];
#pragma unroll
    for (int i = 0; i < 2; i++)
#pragma unroll
        for (int j = 0; j < 8; j++)
#pragma unroll
            for (int k = 0; k < 4; k++) acc[i][j][k] = 0.f;

    const int NC = K / KT;

    auto load_tile = [&](int c, int buf) {
        const float* Ag = A  + (size_t)row0 * K + c * KT;
        const float* Bg = Bt + (size_t)col0 * K + c * KT;
        const uint32_t ab = sbase + (uint32_t)buf * 2 * MATB;
        const uint32_t bb = ab + MATB;
#pragma unroll
        for (int i = 0; i < 4; i++) {
            int id = tid + i * 256;
            int r = id >> 3, c4 = id & 7;
            uint32_t off = (uint32_t)(r * PAD + c4 * 4) * 4;
            cp_async16(ab + off, Ag + (size_t)r * K + c4 * 4);
            cp_async16(bb + off, Bg + (size_t)r * K + c4 * 4);
        }
        cp_commit();
    };

    load_tile(0, 0);

    const int arow = wm * 32 + (lane & 15);
    const int acol = (lane >> 4) << 2;
    const int brow = wn * 64 + ((lane >> 4) << 3) + (lane & 7);
    const int bcol = ((lane >> 3) & 1) << 2;

    for (int c = 0; c < NC; c++) {
        const int buf = c & 1;
        cp_wait<0>();
        __syncthreads();
        if (c + 1 < NC) load_tile(c + 1, buf ^ 1);

        const uint32_t au = sbase + (uint32_t)buf * 2 * MATB;
        const uint32_t bu = au + MATB;

#pragma unroll
        for (int ks = 0; ks < 4; ks++) {
            const int ck = ks * 8;
            uint32_t afr[2][4], bfr[4][4];
#pragma unroll
            for (int mi = 0; mi < 2; mi++)
                ldsm_x4u(afr[mi], au + (uint32_t)(((arow + mi * 16) * PAD) + ck + acol) * 4);
#pragma unroll
            for (int nip = 0; nip < 4; nip++)
                ldsm_x4u(bfr[nip], bu + (uint32_t)(((brow + nip * 16) * PAD) + ck + bcol) * 4);
#pragma unroll
            for (int mi = 0; mi < 2; mi++)
#pragma unroll
                for (int ni = 0; ni < 8; ni++)
                    mma_tf32u(acc[mi][ni], afr[mi],
                              bfr[ni >> 1][(ni & 1) * 2], bfr[ni >> 1][(ni & 1) * 2 + 1]);
        }
    }

    const int qr = lane >> 2;
    const int qc = (lane & 3) * 2;
#pragma unroll
    for (int mi = 0; mi < 2; mi++) {
#pragma unroll
        for (int ni = 0; ni < 8; ni++) {
            int col = col0 + wn * 64 + ni * 8 + qc;
            float b0 = bias[col], b1 = bias[col + 1];
            int r0 = row0 + wm * 32 + mi * 16 + qr;
            float v0 = acc[mi][ni][0] + b0;
            float v1 = acc[mi][ni][1] + b1;
            float v2 = acc[mi][ni][2] + b0;
            float v3 = acc[mi][ni][3] + b1;
            if (relu) {
                v0 = fmaxf(v0, 0.f); v1 = fmaxf(v1, 0.f);
                v2 = fmaxf(v2, 0.f); v3 = fmaxf(v3, 0.f);
            }
            if (round_out) {
                v0 = tf32r(v0); v1 = tf32r(v1);
                v2 = tf32r(v2); v3 = tf32r(v3);
            }
            *(float2*)(C + (size_t)r0 * N + col)       = make_float2(v0, v1);
            *(float2*)(C + (size_t)(r0 + 8) * N + col) = make_float2(v2, v3);
        }
    }
}

__global__ void __launch_bounds__(256)
gemm_tf32(const float* __restrict__ A, const float* __restrict__ Bt,
          const float* __restrict__ bias, float* __restrict__ C,
          int M, int K, int N, int relu, int round_out)
{
    extern __shared__ float sm[];
    gemm_body(A, Bt, bias, C, K, N, relu, round_out,
              blockIdx.y * 128, blockIdx.x * 128, sm);
}

// merged QKV: blockIdx.z selects (A, W, bias, C); per-CTA code identical
__global__ void __launch_bounds__(256)
gemm_tf32_qkv(const float* A0, const float* A1, const float* A2,
              const float* W0, const float* W1, const float* W2,
              const float* b0, const float* b1, const float* b2,
              float* C0, float* C1, float* C2,
              int M, int K, int N)
{
    extern __shared__ float sm[];
    const float *A, *W, *bb;
    float* C;
    if (blockIdx.z == 0)      { A = A0; W = W0; bb = b0; C = C0; }
    else if (blockIdx.z == 1) { A = A1; W = W1; bb = b1; C = C1; }
    else                      { A = A2; W = W2; bb = b2; C = C2; }
    gemm_body(A, W, bb, C, K, N, 0, 1, blockIdx.y * 128, blockIdx.x * 128, sm);
}

// ---------------- fused flash attention (R11 version, known-good) ----------------
#define QT 64
#define KTL 128
#define QS 68
#define VS 132
#define FSMEM ((QT*QS + KTL*QS + 64*VS + 256) * 4)   // 87040 B

__global__ void __launch_bounds__(256, 2)
flash_kernel(const float* __restrict__ Qg, const float* __restrict__ Kg,
             const float* __restrict__ Vtg, const int* __restrict__ mask,
             float* __restrict__ ctx)
{
    extern __shared__ float sf[];
    float* Qs  = sf;                   // 64 x QS
    float* Ks  = Qs + QT * QS;         // 128 x QS  (K tile; P aliases)
    float* Vts = Ks + KTL * QS;        // 64 x VS
    float* Ps  = Ks;                   // alias
    float* tmpM = Vts + 64 * VS;       // 128
    float* tmpS = tmpM + 128;          // 128

    const int tid = threadIdx.x;
    const int wid = tid >> 5, lane = tid & 31;
    const int wm = wid & 3, wn = wid >> 2;
    const int qr = lane >> 2, qc = lane & 3;
    const int bh = blockIdx.y, b = bh >> 4, h = bh & 15;
    const int q0 = blockIdx.x * QT;

    const uint32_t qs_u = smem_u32(Qs), ks_u = smem_u32(Ks), vs_u = smem_u32(Vts);
    const uint32_t ps_u = ks_u;

    const int arow = wm * 16 + (lane & 15);
    const int acol = (lane >> 4) << 2;
    const int brow = ((lane >> 4) << 3) + (lane & 7);
    const int bcol = ((lane >> 3) & 1) << 2;

    // load Q tile (once)
#pragma unroll
    for (int i = 0; i < 4; i++) {
        int id = tid + i * 256;
        int r = id >> 4, ch = id & 15;
        cp_async16(qs_u + (uint32_t)(r * QS + ch * 4) * 4,
                   Qg + (size_t)(b * Sq + q0 + r) * Eq + h * 64 + ch * 4);
    }
    cp_commit();

    float m0 = -INFINITY, m1 = -INFINITY;
    float l0 = 0.f, l1 = 0.f;
    float acc_o[4][4] = {};

    const int rloc = wm * 16 + qr;

    for (int kt = 0; kt < Sq / KTL; kt++) {
#pragma unroll
        for (int i = 0; i < 8; i++) {
            int id = tid + i * 256;
            int r = id >> 4, ch = id & 15;
            cp_async16(ks_u + (uint32_t)(r * QS + ch * 4) * 4,
                       Kg + (size_t)(b * Sq + kt * KTL + r) * Eq + h * 64 + ch * 4);
        }
#pragma unroll
        for (int i = 0; i < 8; i++) {
            int id = tid + i * 256;
            int r = id >> 5, ch = id & 31;
            cp_async16(vs_u + (uint32_t)(r * VS + ch * 4) * 4,
                       Vtg + (size_t)(b * Eq + h * 64 + r) * Sq + kt * KTL + ch * 4);
        }
        cp_commit();
        cp_wait<0>();
        __syncthreads();

        // S = Q @ K^T
        float acc_s[8][4];
#pragma unroll
        for (int ni = 0; ni < 8; ni++)
#pragma unroll
            for (int k = 0; k < 4; k++) acc_s[ni][k] = 0.f;
#pragma unroll
        for (int ks = 0; ks < 8; ks++) {
            const int ck = ks * 8;
            uint32_t afr[4];
            ldsm_x4u(afr, qs_u + (uint32_t)(arow * QS + ck + acol) * 4);
#pragma unroll
            for (int nip = 0; nip < 4; nip++) {
                uint32_t bfr[4];
                ldsm_x4u(bfr, ks_u + (uint32_t)((wn * 64 + nip * 16 + brow) * QS + ck + bcol) * 4);
                mma_tf32u(acc_s[nip * 2],     afr, bfr[0], bfr[1]);
                mma_tf32u(acc_s[nip * 2 + 1], afr, bfr[2], bfr[3]);
            }
        }

        // mask + rsqrt, row max
        float mr0 = -INFINITY, mr1 = -INFINITY;
#pragma unroll
        for (int ni = 0; ni < 8; ni++) {
            int colg = kt * KTL + wn * 64 + ni * 8 + qc * 2;
            int mk0 = mask[b * Sq + colg], mk1 = mask[b * Sq + colg + 1];
            float s0 = mk0 ? rsqrtf(acc_s[ni][0]) : -INFINITY;
            float s1 = mk1 ? rsqrtf(acc_s[ni][1]) : -INFINITY;
            float s2 = mk0 ? rsqrtf(acc_s[ni][2]) : -INFINITY;
            float s3 = mk1 ? rsqrtf(acc_s[ni][3]) : -INFINITY;
            acc_s[ni][0] = s0; acc_s[ni][1] = s1; acc_s[ni][2] = s2; acc_s[ni][3] = s3;
            mr0 = fmaxf(mr0, fmaxf(s0, s1));
            mr1 = fmaxf(mr1, fmaxf(s2, s3));
        }
#pragma unroll
        for (int o = 1; o < 4; o <<= 1) {
            mr0 = fmaxf(mr0, __shfl_xor_sync(0xffffffffu, mr0, o));
            mr1 = fmaxf(mr1, __shfl_xor_sync(0xffffffffu, mr1, o));
        }
        if (qc == 0) { tmpM[wn * 64 + rloc] = mr0; tmpM[wn * 64 + rloc + 8] = mr1; }
        __syncthreads();
        float mt0 = fmaxf(tmpM[rloc],     tmpM[64 + rloc]);
        float mt1 = fmaxf(tmpM[rloc + 8], tmpM[64 + rloc + 8]);
        float mn0 = fmaxf(m0, mt0), mn1 = fmaxf(m1, mt1);
        float mn0s = (mn0 == -INFINITY) ? 0.f : mn0;
        float mn1s = (mn1 == -INFINITY) ? 0.f : mn1;
        float sc0 = __expf(m0 - mn0s);
        float sc1 = __expf(m1 - mn1s);
        m0 = mn0; m1 = mn1;

        // exp, row sum, store P (tf32-rounded) into dead K region
        float sr0 = 0.f, sr1 = 0.f;
#pragma unroll
        for (int ni = 0; ni < 8; ni++) {
            float p0 = __expf(acc_s[ni][0] - mn0s);
            float p1 = __expf(acc_s[ni][1] - mn0s);
            float p2 = __expf(acc_s[ni][2] - mn1s);
            float p3 = __expf(acc_s[ni][3] - mn1s);
            sr0 += p0 + p1; sr1 += p2 + p3;
            int colp = wn * 64 + ni * 8 + qc * 2;
            Ps[rloc * VS + colp]           = tf32r(p0);
            Ps[rloc * VS + colp + 1]       = tf32r(p1);
            Ps[(rloc + 8) * VS + colp]     = tf32r(p2);
            Ps[(rloc + 8) * VS + colp + 1] = tf32r(p3);
        }
#pragma unroll
        for (int o = 1; o < 4; o <<= 1) {
            sr0 += __shfl_xor_sync(0xffffffffu, sr0, o);
            sr1 += __shfl_xor_sync(0xffffffffu, sr1, o);
        }
        if (qc == 0) { tmpS[wn * 64 + rloc] = sr0; tmpS[wn * 64 + rloc + 8] = sr1; }
        __syncthreads();
        l0 = l0 * sc0 + tmpS[rloc]     + tmpS[64 + rloc];
        l1 = l1 * sc1 + tmpS[rloc + 8] + tmpS[64 + rloc + 8];

#pragma unroll
        for (int ni = 0; ni < 4; ni++) {
            acc_o[ni][0] *= sc0; acc_o[ni][1] *= sc0;
            acc_o[ni][2] *= sc1; acc_o[ni][3] *= sc1;
        }

        // O += P @ V
#pragma unroll
        for (int ks = 0; ks < 16; ks++) {
            const int ck = ks * 8;
            uint32_t afr[4];
            ldsm_x4u(afr, ps_u + (uint32_t)(arow * VS + ck + acol) * 4);
#pragma unroll
            for (int nip = 0; nip < 2; nip++) {
                uint32_t bfr[4];
                ldsm_x4u(bfr, vs_u + (uint32_t)((wn * 32 + nip * 16 + brow) * VS + ck + bcol) * 4);
                mma_tf32u(acc_o[nip * 2],     afr, bfr[0], bfr[1]);
                mma_tf32u(acc_o[nip * 2 + 1], afr, bfr[2], bfr[3]);
            }
        }
        __syncthreads();
    }

    // epilogue
    float inv0 = 1.f / l0, inv1 = 1.f / l1;
#pragma unroll
    for (int ni = 0; ni < 4; ni++) {
        int col = h * 64 + wn * 32 + ni * 8 + qc * 2;
        size_t r = (size_t)(b * Sq + q0 + rloc);
        *(float2*)(ctx + r * Eq + col) =
            make_float2(tf32r(acc_o[ni][0] * inv0), tf32r(acc_o[ni][1] * inv0));
        *(float2*)(ctx + (r + 8) * Eq + col) =
            make_float2(tf32r(acc_o[ni][2] * inv1), tf32r(acc_o[ni][3] * inv1));
    }
}

// ---------------- out = LayerNorm(A + R); optional tf32-rounded copy ----------------
__global__ void __launch_bounds__(256)
add_ln_kernel(const float* __restrict__ A, const float* __restrict__ R,
              const float* __restrict__ g, const float* __restrict__ be,
              float* __restrict__ out, float* __restrict__ out_r)
{
    const size_t row = blockIdx.x;
    const int tid = threadIdx.x;
    const int lane = tid & 31, warp = tid >> 5;
    __shared__ float red[8];
    const float* pa = A + row * Eq;
    const float* pr = R + row * Eq;

    float v[4];
    float s = 0.f;
#pragma unroll
    for (int i = 0; i < 4; i++) {
        v[i] = pa[tid + i * 256] + pr[tid + i * 256];
        s += v[i];
    }
#pragma unroll
    for (int o = 16; o; o >>= 1) s += __shfl_xor_sync(0xffffffffu, s, o);
    if (lane == 0) red[warp] = s;
    __syncthreads();
    if (tid == 0) {
        float t = 0.f;
#pragma unroll
        for (int i = 0; i < 8; i++) t += red[i];
        red[0] = t;
    }
    __syncthreads();
    const float mean = red[0] * (1.f / Eq);
    __syncthreads();

    float s2 = 0.f;
#pragma unroll
    for (int i = 0; i < 4; i++) {
        float d = v[i] - mean;
        s2 += d * d;
    }
#pragma unroll
    for (int o = 16; o; o >>= 1) s2 += __shfl_xor_sync(0xffffffffu, s2, o);
    if (lane == 0) red[warp] = s2;
    __syncthreads();
    if (tid == 0) {
        float t = 0.f;
#pragma unroll
        for (int i = 0; i < 8; i++) t += red[i];
        red[0] = t;
    }
    __syncthreads();
    const float inv = rsqrtf(red[0] * (1.f / Eq) + LN_EPS);

#pragma unroll
    for (int i = 0; i < 4; i++) {
        int c = tid + i * 256;
        float o = (v[i] - mean) * inv * g[c] + be[c];
        out[row * Eq + c] = o;
        if (out_r) out_r[row * Eq + c] = tf32r(o);
    }
}

// ---------------- host launch ----------------
extern "C" void kernel_launch(void* const* d_in, const int* in_sizes, int n_in,
                              void* d_out, int out_size)
{
    const float* value = (const float*)d_in[0];
    const float* key   = (const float*)d_in[1];
    const float* query = (const float*)d_in[2];
    const int*   mask  = (const int*)d_in[3];
    const float* Wv = (const float*)d_in[4];
    const float* bv = (const float*)d_in[5];
    const float* Wk = (const float*)d_in[6];
    const float* bk = (const float*)d_in[7];
    const float* Wq = (const float*)d_in[8];
    const float* bq = (const float*)d_in[9];
    const float* Wo = (const float*)d_in[10];
    const float* bo = (const float*)d_in[11];
    const float* W1 = (const float*)d_in[12];
    const float* b1 = (const float*)d_in[13];
    const float* W2 = (const float*)d_in[14];
    const float* b2 = (const float*)d_in[15];
    const float* g1  = (const float*)d_in[16];
    const float* be1 = (const float*)d_in[17];
    const float* g2  = (const float*)d_in[18];
    const float* be2 = (const float*)d_in[19];
    float* out = (float*)d_out;

    float *pV, *pK, *pQ, *pVt, *pCtx, *pAo, *pX, *pXr, *pH, *pFf;
    float *pVr, *pKr, *pQr;
    float *pWvt, *pWkt, *pWqt, *pWot, *pW1t, *pW2t;
    cudaGetSymbolAddress((void**)&pV,   g_V);
    cudaGetSymbolAddress((void**)&pK,   g_K);
    cudaGetSymbolAddress((void**)&pQ,   g_Q);
    cudaGetSymbolAddress((void**)&pVt,  g_Vt);
    cudaGetSymbolAddress((void**)&pCtx, g_ctx);
    cudaGetSymbolAddress((void**)&pAo,  g_ao);
    cudaGetSymbolAddress((void**)&pX,   g_x);
    cudaGetSymbolAddress((void**)&pXr,  g_xr);
    cudaGetSymbolAddress((void**)&pH,   g_h);
    cudaGetSymbolAddress((void**)&pFf,  g_ff);
    cudaGetSymbolAddress((void**)&pVr,  g_vr);
    cudaGetSymbolAddress((void**)&pKr,  g_kr);
    cudaGetSymbolAddress((void**)&pQr,  g_qr);
    cudaGetSymbolAddress((void**)&pWvt, g_Wvt);
    cudaGetSymbolAddress((void**)&pWkt, g_Wkt);
    cudaGetSymbolAddress((void**)&pWqt, g_Wqt);
    cudaGetSymbolAddress((void**)&pWot, g_Wot);
    cudaGetSymbolAddress((void**)&pW1t, g_W1t);
    cudaGetSymbolAddress((void**)&pW2t, g_W2t);

    cudaFuncSetAttribute(gemm_tf32, cudaFuncAttributeMaxDynamicSharedMemorySize, GSMEM);
    cudaFuncSetAttribute(gemm_tf32_qkv, cudaFuncAttributeMaxDynamicSharedMemorySize, GSMEM);
    cudaFuncSetAttribute(flash_kernel, cudaFuncAttributeMaxDynamicSharedMemorySize, FSMEM);

    const int M = Bq * Sq;  // 4096
    dim3 blk(256);

    // ONE merged prep launch: 6 weight transposes + 3 activation round passes
    prep_kernel<<<PREP_BLOCKS, blk>>>(
        Wv, Wk, Wq, Wo, W1, W2,
        pWvt, pWkt, pWqt, pWot, pW1t, pW2t,
        value, key, query, pVr, pKr, pQr);

    // QKV projections merged into ONE launch (z selects V/K/Q)
    dim3 grid_qkv(Eq / 128, M / 128, 3);
    gemm_tf32_qkv<<<grid_qkv, blk, GSMEM>>>(
        pVr, pKr, pQr, pWvt, pWkt, pWqt, bv, bk, bq, pV, pK, pQ, M, Eq, Eq);

    // V transpose per batch
    vtrans_kernel<<<dim3(Sq / 32, Eq / 32, Bq), blk>>>(pV, pVt);

    // fused flash attention -> ctx (tf32-rounded)
    flash_kernel<<<dim3(Sq / QT, Bq * Hh), blk, FSMEM>>>(pQ, pK, pVt, mask, pCtx);

    // output projection
    dim3 grid_e(Eq / 128, M / 128);
    gemm_tf32<<<grid_e, blk, GSMEM>>>(pCtx, pWot, bo, pAo, M, Eq, Eq, 0, 0);

    // x = LN(attn_out + query); tf32-rounded copy for FFN1
    add_ln_kernel<<<M, blk>>>(pAo, query, g1, be1, pX, pXr);

    // FFN1
    dim3 grid_ff1(FFq / 128, M / 128);
    gemm_tf32<<<grid_ff1, blk, GSMEM>>>(pXr, pW1t, b1, pH, M, Eq, FFq, 1, 1);

    // FFN2
    dim3 grid_ff2(Eq / 128, M / 128);
    gemm_tf32<<<grid_ff2, blk, GSMEM>>>(pH, pW2t, b2, pFf, M, FFq, Eq, 0, 0);

    // out = LN(ff + x)
    add_ln_kernel<<<M, blk>>>(pFf, pX, g2, be2, out, nullptr);
}